// round 4
// baseline (speedup 1.0000x reference)
#include <cuda_runtime.h>
#include <cuda_fp16.h>

#define NB   8
#define TOUT 256
#define TIN  512
#define LH   128
#define G4   512
#define DIN  128
#define DATT 128

#define OUT_X_ELEMS (NB*TOUT*(LH+DATT))
#define OUT_H_OFF   (OUT_X_ELEMS)
#define OUT_C_OFF   (OUT_X_ELEMS + NB*LH)

// ---- LSTM config ----
#define KREG 88
#define KSM  (LH - KREG)                 // 40
#define WSTRIDE 44                       // padded row (floats) for w_sT
#define LSTM_DSMEM (512 * WSTRIDE * 4)   // 90112 B

// ---- attn config ----
#define AQ 8
#define KPAD 66
#define A_KEYS_OFF 0
#define A_KEYS_SZ  (128 * KPAD * 4)            // half2[128][66] = 33792
#define A_QH_OFF   (A_KEYS_OFF + A_KEYS_SZ)
#define A_QH_SZ    (AQ * 64 * 4)               // 2048
#define A_W3_OFF   (A_QH_OFF + A_QH_SZ)
#define A_W3_SZ    (64 * 4)
#define A_SC_OFF   (A_W3_OFF + A_W3_SZ)
#define A_SC_SZ    (AQ * 512 * 4)              // 16384
#define ATTN_DSMEM (A_SC_OFF + A_SC_SZ)        // 52480

// ---- weighted (mma) config ----
#define W_APAD 520                             // attn smem row pad (halves)
#define W_BPAD 18                              // bT row pad (halves)
#define W_AS_SZ (64 * W_APAD * 2)              // 66560
#define W_BT_SZ (128 * W_BPAD * 2)             // 4608
#define WEIGHTED_DSMEM (W_AS_SZ + W_BT_SZ)     // 71168

__device__ float  g_keys[NB*TIN*LH];
__device__ float  g_xz[NB*TOUT*G4];
__device__ float  g_q[NB*TOUT*LH];
__device__ __half g_attn_h[NB*TOUT*TIN];
__device__ __half g_att_h[NB*TIN*DATT];

__device__ __forceinline__ float tanh_hw(float x) {
    float y;
    asm("tanh.approx.f32 %0, %1;" : "=f"(y) : "f"(x));
    return y;
}
__device__ __forceinline__ float sigm_hw(float x) {
    return fmaf(0.5f, tanh_hw(0.5f * x), 0.5f);
}
__device__ __forceinline__ __half2 tanh_h2(__half2 x) {
    unsigned r, xi = *reinterpret_cast<unsigned*>(&x);
    asm("tanh.approx.f16x2 %0, %1;" : "=r"(r) : "r"(xi));
    return *reinterpret_cast<__half2*>(&r);
}
__device__ __forceinline__ __half2 u2h2(unsigned u) {
    __half2 h; *reinterpret_cast<unsigned*>(&h) = u; return h;
}

// ---------------------------------------------------------------------------
// K1: fused keys + xz projections (also emits attended in half).
// ---------------------------------------------------------------------------
__global__ void __launch_bounds__(128) proj_kernel(
    const float* __restrict__ att, const float* __restrict__ W1,
    const float* __restrict__ b1,  float* __restrict__ keys,
    const float* __restrict__ inp, const float* __restrict__ Wk,
    const float* __restrict__ lbias, float* __restrict__ xz,
    __half* __restrict__ att_h)
{
    int bid = blockIdx.x;
    int j = threadIdx.x;
    __shared__ float a[DIN];
    if (bid < NB * TIN) {
        int row = bid;
        float av = att[row * DATT + j];
        a[j] = av;
        att_h[row * DATT + j] = __float2half(av);
        __syncthreads();
        float acc = b1[j];
        #pragma unroll 8
        for (int l = 0; l < DATT; l++)
            acc += a[l] * W1[l * LH + j];
        keys[row * LH + j] = acc;
    } else {
        int row = bid - NB * TIN;
        a[j] = inp[row * DIN + j];
        __syncthreads();
        float a0 = lbias[j], a1 = lbias[j + 128],
              a2 = lbias[j + 256], a3 = lbias[j + 384];
        #pragma unroll 4
        for (int d = 0; d < DIN; d++) {
            float v = a[d];
            const float* wr = Wk + d * G4;
            a0 += v * wr[j];
            a1 += v * wr[j + 128];
            a2 += v * wr[j + 256];
            a3 += v * wr[j + 384];
        }
        float* o = xz + row * G4;
        o[j] = a0; o[j + 128] = a1; o[j + 256] = a2; o[j + 384] = a3;
    }
}

// ---------------------------------------------------------------------------
// K2: LSTM scan. 1 CTA/batch, 512 threads. Wr rows 0..KREG-1 in registers,
//     KREG..127 transposed in smem (LDS.128, conflict-free per phase).
// ---------------------------------------------------------------------------
__global__ void __launch_bounds__(512, 1) lstm_kernel(
    const float* __restrict__ xz, const float* __restrict__ Wr,
    float* __restrict__ out)
{
    int b = blockIdx.x;
    int j = threadIdx.x;
    __shared__ float h_s[LH];
    __shared__ float z_s[G4];
    extern __shared__ float w_sT[];       // [512][WSTRIDE]

    // transposed smem weights: w_sT[j][kk] = Wr[KREG+kk][j]
    #pragma unroll 4
    for (int kk = 0; kk < KSM; kk++)
        w_sT[j * WSTRIDE + kk] = Wr[(KREG + kk) * G4 + j];

    float wr[KREG];
    #pragma unroll
    for (int k = 0; k < KREG; k++)
        wr[k] = Wr[k * G4 + j];

    if (j < LH) h_s[j] = 0.0f;
    float c = 0.0f;
    __syncthreads();

    const float* xzb = xz + b * TOUT * G4;
    float xnext = xzb[j];
    bool is_g = (j >= 2 * LH) && (j < 3 * LH);

    for (int t = 0; t < TOUT; t++) {
        float acc0 = xnext;
        float acc1 = 0.0f;
        if (t + 1 < TOUT) xnext = xzb[(t + 1) * G4 + j];

        #pragma unroll
        for (int kk = 0; kk < KREG / 4; kk++) {
            float4 h4 = *reinterpret_cast<const float4*>(&h_s[kk * 4]);
            acc0 += h4.x * wr[kk * 4 + 0];
            acc1 += h4.y * wr[kk * 4 + 1];
            acc0 += h4.z * wr[kk * 4 + 2];
            acc1 += h4.w * wr[kk * 4 + 3];
        }
        #pragma unroll
        for (int kk = 0; kk < KSM / 4; kk++) {
            float4 h4 = *reinterpret_cast<const float4*>(&h_s[KREG + kk * 4]);
            float4 w4 = *reinterpret_cast<const float4*>(&w_sT[j * WSTRIDE + kk * 4]);
            acc0 += h4.x * w4.x;
            acc1 += h4.y * w4.y;
            acc0 += h4.z * w4.z;
            acc1 += h4.w * w4.w;
        }
        float z = acc0 + acc1;
        z_s[j] = is_g ? tanh_hw(z) : sigm_hw(z);   // nonlinearity in parallel
        __syncthreads();
        if (j < LH) {
            c = z_s[LH + j] * c + z_s[j] * z_s[2 * LH + j];
            float h = z_s[3 * LH + j] * tanh_hw(c);
            h_s[j] = h;
            out[(b * TOUT + t) * (LH + DATT) + j] = h;
        }
        __syncthreads();
    }
    if (j < LH) {
        out[OUT_H_OFF + b * LH + j] = h_s[j];
        out[OUT_C_OFF + b * LH + j] = c;
    }
}

// ---------------------------------------------------------------------------
// K3: q = x @ W2 + b2
// ---------------------------------------------------------------------------
__global__ void __launch_bounds__(128) q_kernel(
    const float* __restrict__ out, const float* __restrict__ W2,
    const float* __restrict__ b2, float* __restrict__ q)
{
    int row = blockIdx.x;
    __shared__ float a[LH];
    a[threadIdx.x] = out[row * (LH + DATT) + threadIdx.x];
    __syncthreads();
    int j = threadIdx.x;
    float acc = b2[j];
    #pragma unroll 8
    for (int l = 0; l < LH; l++)
        acc += a[l] * W2[l * LH + j];
    q[row * LH + j] = acc;
}

// ---------------------------------------------------------------------------
// K4: scores + softmax. half2 HFMA2 accumulation (promote every 8 iters),
//     LDS.64 everywhere. Outputs attention weights in HALF.
//     512 thr: ql = tid>>6 (8 q-rows), kk = tid&63 (2 keys/chunk of 128).
// ---------------------------------------------------------------------------
__global__ void __launch_bounds__(512, 2) attn_kernel(
    const float* __restrict__ keys, const float* __restrict__ q,
    const float* __restrict__ W3, __half* __restrict__ attn_h)
{
    extern __shared__ char sm[];
    __half2* keys_h = reinterpret_cast<__half2*>(sm + A_KEYS_OFF);  // [128][KPAD]
    __half2* qh     = reinterpret_cast<__half2*>(sm + A_QH_OFF);    // [AQ][64]
    __half2* w3h    = reinterpret_cast<__half2*>(sm + A_W3_OFF);    // [64]
    float*   sc     = reinterpret_cast<float*>(sm + A_SC_OFF);      // [AQ][512]

    int b  = blockIdx.y;
    int q0 = blockIdx.x * AQ;
    int tid = threadIdx.x;

    for (int i = tid; i < AQ * 64; i += 512) {
        int r = i >> 6, l2 = i & 63;
        float2 v = *reinterpret_cast<const float2*>(&q[(b * TOUT + q0 + r) * LH + 2 * l2]);
        qh[r * 64 + l2] = __floats2half2_rn(v.x, v.y);
    }
    if (tid < 64) {
        float2 v = *reinterpret_cast<const float2*>(&W3[2 * tid]);
        w3h[tid] = __floats2half2_rn(v.x, v.y);
    }

    int ql = tid >> 6;            // 0..7
    int kk = tid & 63;
    const float* kb = keys + b * TIN * LH;
    const unsigned* qrow = reinterpret_cast<const unsigned*>(qh) + ql * 64;
    const unsigned* w3u  = reinterpret_cast<const unsigned*>(w3h);
    const unsigned* keyu = reinterpret_cast<const unsigned*>(keys_h);

    for (int c = 0; c < 4; c++) {
        __syncthreads();
        for (int i = tid; i < 128 * 64; i += 512) {
            int k = i >> 6, l2 = i & 63;
            float2 v = *reinterpret_cast<const float2*>(&kb[(c * 128 + k) * LH + 2 * l2]);
            keys_h[k * KPAD + l2] = __floats2half2_rn(v.x, v.y);
        }
        __syncthreads();

        float accf0 = 0.0f, accf1 = 0.0f;
        #pragma unroll
        for (int g = 0; g < 8; g++) {
            __half2 a0 = __floats2half2_rn(0.f, 0.f);
            __half2 a1 = a0;
            #pragma unroll
            for (int u = 0; u < 8; u += 2) {
                int l2 = g * 8 + u;
                uint2 k0 = *reinterpret_cast<const uint2*>(&keyu[kk * KPAD + l2]);
                uint2 k1 = *reinterpret_cast<const uint2*>(&keyu[(kk + 64) * KPAD + l2]);
                uint2 qv = *reinterpret_cast<const uint2*>(&qrow[l2]);
                uint2 wv = *reinterpret_cast<const uint2*>(&w3u[l2]);
                a0 = __hfma2(tanh_h2(__hadd2(u2h2(k0.x), u2h2(qv.x))), u2h2(wv.x), a0);
                a0 = __hfma2(tanh_h2(__hadd2(u2h2(k0.y), u2h2(qv.y))), u2h2(wv.y), a0);
                a1 = __hfma2(tanh_h2(__hadd2(u2h2(k1.x), u2h2(qv.x))), u2h2(wv.x), a1);
                a1 = __hfma2(tanh_h2(__hadd2(u2h2(k1.y), u2h2(qv.y))), u2h2(wv.y), a1);
            }
            float2 f0 = __half22float2(a0); accf0 += f0.x + f0.y;
            float2 f1 = __half22float2(a1); accf1 += f1.x + f1.y;
        }
        sc[ql * 512 + c * 128 + kk]      = accf0;
        sc[ql * 512 + c * 128 + kk + 64] = accf1;
    }
    __syncthreads();

    int w = tid >> 5, lane = tid & 31;
    if (w < AQ) {
        const float* row = sc + w * 512;
        float v[16], mx = -1e30f;
        #pragma unroll
        for (int i = 0; i < 16; i++) {
            v[i] = row[lane + 32 * i];
            mx = fmaxf(mx, v[i]);
        }
        #pragma unroll
        for (int off = 16; off >= 1; off >>= 1)
            mx = fmaxf(mx, __shfl_xor_sync(0xffffffffu, mx, off));
        float s = 0.0f;
        #pragma unroll
        for (int i = 0; i < 16; i++) {
            v[i] = __expf(v[i] - mx);
            s += v[i];
        }
        #pragma unroll
        for (int off = 16; off >= 1; off >>= 1)
            s += __shfl_xor_sync(0xffffffffu, s, off);
        float inv = 1.0f / s;
        __half* orow = attn_h + (b * TOUT + q0 + w) * TIN;
        #pragma unroll
        for (int i = 0; i < 16; i++)
            orow[lane + 32 * i] = __float2half(v[i] * inv);
    }
}

// ---------------------------------------------------------------------------
// K5: weighted = attn @ attended via mma.sync m16n8k16 (f16 x f16 -> f32).
//     CTA: 128 thr (4 warps), 64 q-rows, full N=128, K=512 in 32 steps.
// ---------------------------------------------------------------------------
__global__ void __launch_bounds__(128) weighted_mma_kernel(
    const __half* __restrict__ attn_h, const __half* __restrict__ att_h,
    float* __restrict__ out)
{
    extern __shared__ char sm[];
    __half* a_s = reinterpret_cast<__half*>(sm);              // [64][W_APAD]
    __half* bT  = reinterpret_cast<__half*>(sm + W_AS_SZ);    // [128][W_BPAD]

    int b  = blockIdx.y;
    int m0 = blockIdx.x * 64;
    int tid = threadIdx.x;
    int wid = tid >> 5, lane = tid & 31;

    // stage attn tile [64][512] halves
    for (int i = tid; i < 64 * 64; i += 128) {
        int r = i >> 6, cc = i & 63;
        uint4 v = *reinterpret_cast<const uint4*>(
            &attn_h[(b * TOUT + m0 + r) * TIN + cc * 8]);
        *reinterpret_cast<uint4*>(&a_s[r * W_APAD + cc * 8]) = v;
    }

    float acc[16][4];
    #pragma unroll
    for (int nt = 0; nt < 16; nt++)
        #pragma unroll
        for (int i = 0; i < 4; i++) acc[nt][i] = 0.0f;

    int r4 = lane >> 2;          // 0..7
    int c2 = (lane & 3) * 2;

    for (int ks = 0; ks < 32; ks++) {
        __syncthreads();
        // stage bT[d][kk] = att_h[b][ks*16+kk][d]
        #pragma unroll
        for (int kk = 0; kk < 16; kk++)
            bT[tid * W_BPAD + kk] = att_h[(b * TIN + ks * 16 + kk) * DATT + tid];
        __syncthreads();

        int k0 = ks * 16;
        const __half* arow0 = &a_s[(wid * 16 + r4) * W_APAD + k0 + c2];
        const __half* arow1 = arow0 + 8 * W_APAD;
        unsigned a0 = *reinterpret_cast<const unsigned*>(arow0);
        unsigned a1 = *reinterpret_cast<const unsigned*>(arow1);
        unsigned a2 = *reinterpret_cast<const unsigned*>(arow0 + 8);
        unsigned a3 = *reinterpret_cast<const unsigned*>(arow1 + 8);

        #pragma unroll
        for (int nt = 0; nt < 16; nt++) {
            const __half* brow = &bT[(nt * 8 + r4) * W_BPAD + c2];
            unsigned b0 = *reinterpret_cast<const unsigned*>(brow);
            unsigned b1 = *reinterpret_cast<const unsigned*>(brow + 8);
            asm volatile(
                "mma.sync.aligned.m16n8k16.row.col.f32.f16.f16.f32 "
                "{%0,%1,%2,%3},{%4,%5,%6,%7},{%8,%9},{%0,%1,%2,%3};"
                : "+f"(acc[nt][0]), "+f"(acc[nt][1]),
                  "+f"(acc[nt][2]), "+f"(acc[nt][3])
                : "r"(a0), "r"(a1), "r"(a2), "r"(a3), "r"(b0), "r"(b1));
        }
    }

    // epilogue: D[row][col] -> out[b][q][128 + col]
    int row0 = m0 + wid * 16 + r4;
    #pragma unroll
    for (int nt = 0; nt < 16; nt++) {
        int col = 128 + nt * 8 + c2;
        float2 v0 = make_float2(acc[nt][0], acc[nt][1]);
        float2 v1 = make_float2(acc[nt][2], acc[nt][3]);
        *reinterpret_cast<float2*>(
            &out[(b * TOUT + row0) * (LH + DATT) + col]) = v0;
        *reinterpret_cast<float2*>(
            &out[(b * TOUT + row0 + 8) * (LH + DATT) + col]) = v1;
    }
}

// ---------------------------------------------------------------------------
extern "C" void kernel_launch(void* const* d_in, const int* in_sizes, int n_in,
                              void* d_out, int out_size)
{
    const float* inputs   = (const float*)d_in[0];
    const float* attended = (const float*)d_in[1];
    const float* Wk       = (const float*)d_in[2];
    const float* Wr       = (const float*)d_in[3];
    const float* lbias    = (const float*)d_in[4];
    const float* W1       = (const float*)d_in[5];
    const float* b1       = (const float*)d_in[6];
    const float* W2       = (const float*)d_in[7];
    const float* b2       = (const float*)d_in[8];
    const float* W3       = (const float*)d_in[9];
    float* out = (float*)d_out;

    cudaFuncSetAttribute(lstm_kernel,
                         cudaFuncAttributeMaxDynamicSharedMemorySize, LSTM_DSMEM);
    cudaFuncSetAttribute(attn_kernel,
                         cudaFuncAttributeMaxDynamicSharedMemorySize, ATTN_DSMEM);
    cudaFuncSetAttribute(weighted_mma_kernel,
                         cudaFuncAttributeMaxDynamicSharedMemorySize, WEIGHTED_DSMEM);

    proj_kernel<<<NB * TIN + NB * TOUT, 128>>>(attended, W1, b1, g_keys,
                                               inputs, Wk, lbias, g_xz, g_att_h);
    lstm_kernel<<<NB, 512, LSTM_DSMEM>>>(g_xz, Wr, out);
    q_kernel<<<NB * TOUT, 128>>>(out, W2, b2, g_q);
    {
        dim3 grid(TOUT / AQ, NB);
        attn_kernel<<<grid, 512, ATTN_DSMEM>>>(g_keys, g_q, W3, g_attn_h);
    }
    {
        dim3 grid(4, NB);
        weighted_mma_kernel<<<grid, 128, WEIGHTED_DSMEM>>>(g_attn_h, g_att_h, out);
    }
    (void)in_sizes; (void)n_in; (void)out_size;
}

// round 5
// speedup vs baseline: 1.2875x; 1.2875x over previous
#include <cuda_runtime.h>
#include <cuda_fp16.h>

#define NB   8
#define TOUT 256
#define TIN  512
#define LH   128
#define G4   512
#define DIN  128
#define DATT 128

#define OUT_X_ELEMS (NB*TOUT*(LH+DATT))
#define OUT_H_OFF   (OUT_X_ELEMS)
#define OUT_C_OFF   (OUT_X_ELEMS + NB*LH)

// ---- LSTM config ----
#define KREG 80
#define KSM  (LH - KREG)                 // 48
#define WSTRIDE 52                       // 48 + 4 pad (floats)
#define LSTM_DSMEM (512 * WSTRIDE * 4)   // 106496 B

// ---- score config ----
#define KPAD 66                          // half2 row stride for 64 half2
#define S_KEYS_SZ (128 * KPAD * 4)       // 33792
#define S_QH_SZ   (8 * 64 * 4)           // 2048
#define S_W3_SZ   (64 * 4)               // 256
#define SCORE_DSMEM (S_KEYS_SZ + S_QH_SZ + S_W3_SZ)   // 36096

__device__ float  g_xz[NB*TOUT*G4];      // 4 MB
__device__ __half g_keys_h[NB*TIN*LH];   // 1 MB
__device__ __half g_q_h[NB*TOUT*LH];     // 0.5 MB
__device__ float  g_sc[NB*TOUT*TIN];     // 4 MB raw scores
__device__ float  g_attn[NB*TOUT*TIN];   // 4 MB softmaxed

__device__ __forceinline__ float tanh_hw(float x) {
    float y;
    asm("tanh.approx.f32 %0, %1;" : "=f"(y) : "f"(x));
    return y;
}
__device__ __forceinline__ float sigm_hw(float x) {
    return fmaf(0.5f, tanh_hw(0.5f * x), 0.5f);
}
__device__ __forceinline__ __half2 tanh_h2(__half2 x) {
    unsigned r, xi = *reinterpret_cast<unsigned*>(&x);
    asm("tanh.approx.f16x2 %0, %1;" : "=r"(r) : "r"(xi));
    return *reinterpret_cast<__half2*>(&r);
}
__device__ __forceinline__ __half2 u2h2(unsigned u) {
    __half2 h; *reinterpret_cast<unsigned*>(&h) = u; return h;
}

// ---------------------------------------------------------------------------
// K1: fused keys(->half) + xz projections.
// ---------------------------------------------------------------------------
__global__ void __launch_bounds__(128) proj_kernel(
    const float* __restrict__ att, const float* __restrict__ W1,
    const float* __restrict__ b1,  __half* __restrict__ keys_h,
    const float* __restrict__ inp, const float* __restrict__ Wk,
    const float* __restrict__ lbias, float* __restrict__ xz)
{
    int bid = blockIdx.x;
    int j = threadIdx.x;
    __shared__ float a[DIN];
    if (bid < NB * TIN) {
        int row = bid;
        a[j] = att[row * DATT + j];
        __syncthreads();
        float acc = b1[j];
        #pragma unroll 8
        for (int l = 0; l < DATT; l++)
            acc += a[l] * W1[l * LH + j];
        keys_h[row * LH + j] = __float2half(acc);
    } else {
        int row = bid - NB * TIN;
        a[j] = inp[row * DIN + j];
        __syncthreads();
        float a0 = lbias[j], a1 = lbias[j + 128],
              a2 = lbias[j + 256], a3 = lbias[j + 384];
        #pragma unroll 4
        for (int d = 0; d < DIN; d++) {
            float v = a[d];
            const float* wr = Wk + d * G4;
            a0 += v * wr[j];
            a1 += v * wr[j + 128];
            a2 += v * wr[j + 256];
            a3 += v * wr[j + 384];
        }
        float* o = xz + row * G4;
        o[j] = a0; o[j + 128] = a1; o[j + 256] = a2; o[j + 384] = a3;
    }
}

// ---------------------------------------------------------------------------
// K2: LSTM scan. KREG=80 rows in regs (fits 124-reg cap, no spills),
//     48 rows transposed in smem (LDS.128 conflict-free).
// ---------------------------------------------------------------------------
__global__ void __launch_bounds__(512, 1) lstm_kernel(
    const float* __restrict__ xz, const float* __restrict__ Wr,
    float* __restrict__ out)
{
    int b = blockIdx.x;
    int j = threadIdx.x;
    __shared__ float h_s[LH];
    __shared__ float z_s[G4];
    extern __shared__ float w_sT[];       // [512][WSTRIDE]

    #pragma unroll 4
    for (int kk = 0; kk < KSM; kk++)
        w_sT[j * WSTRIDE + kk] = Wr[(KREG + kk) * G4 + j];

    float wr[KREG];
    #pragma unroll
    for (int k = 0; k < KREG; k++)
        wr[k] = Wr[k * G4 + j];

    if (j < LH) h_s[j] = 0.0f;
    float c = 0.0f;
    __syncthreads();

    const float* xzb = xz + b * TOUT * G4;
    float xnext = xzb[j];
    bool is_g = (j >= 2 * LH) && (j < 3 * LH);

    for (int t = 0; t < TOUT; t++) {
        float acc0 = xnext;
        float acc1 = 0.0f;
        if (t + 1 < TOUT) xnext = xzb[(t + 1) * G4 + j];

        #pragma unroll
        for (int kk = 0; kk < KREG / 4; kk++) {
            float4 h4 = *reinterpret_cast<const float4*>(&h_s[kk * 4]);
            acc0 += h4.x * wr[kk * 4 + 0];
            acc1 += h4.y * wr[kk * 4 + 1];
            acc0 += h4.z * wr[kk * 4 + 2];
            acc1 += h4.w * wr[kk * 4 + 3];
        }
        #pragma unroll
        for (int kk = 0; kk < KSM / 4; kk++) {
            float4 h4 = *reinterpret_cast<const float4*>(&h_s[KREG + kk * 4]);
            float4 w4 = *reinterpret_cast<const float4*>(&w_sT[j * WSTRIDE + kk * 4]);
            acc0 += h4.x * w4.x;
            acc1 += h4.y * w4.y;
            acc0 += h4.z * w4.z;
            acc1 += h4.w * w4.w;
        }
        float z = acc0 + acc1;
        z_s[j] = is_g ? tanh_hw(z) : sigm_hw(z);
        __syncthreads();
        if (j < LH) {
            c = z_s[LH + j] * c + z_s[j] * z_s[2 * LH + j];
            float h = z_s[3 * LH + j] * tanh_hw(c);
            h_s[j] = h;
            out[(b * TOUT + t) * (LH + DATT) + j] = h;
        }
        __syncthreads();
    }
    if (j < LH) {
        out[OUT_H_OFF + b * LH + j] = h_s[j];
        out[OUT_C_OFF + b * LH + j] = c;
    }
}

// ---------------------------------------------------------------------------
// K3: q = x @ W2 + b2  -> half
// ---------------------------------------------------------------------------
__global__ void __launch_bounds__(128) q_kernel(
    const float* __restrict__ out, const float* __restrict__ W2,
    const float* __restrict__ b2, __half* __restrict__ q_h)
{
    int row = blockIdx.x;
    __shared__ float a[LH];
    a[threadIdx.x] = out[row * (LH + DATT) + threadIdx.x];
    __syncthreads();
    int j = threadIdx.x;
    float acc = b2[j];
    #pragma unroll 8
    for (int l = 0; l < LH; l++)
        acc += a[l] * W2[l * LH + j];
    q_h[row * LH + j] = __float2half(acc);
}

// ---------------------------------------------------------------------------
// K4: raw scores. Grid (TIN/128, TOUT/8, NB) = 1024 CTAs, 512 thr.
//     Each CTA: 8 q-rows x 128 keys x 128 L. Writes f32 scores.
// ---------------------------------------------------------------------------
__global__ void __launch_bounds__(512, 2) score_kernel(
    const __half* __restrict__ keys_h_g, const __half* __restrict__ q_h_g,
    const float* __restrict__ W3, float* __restrict__ sc_g)
{
    extern __shared__ char sm[];
    unsigned* keyu = reinterpret_cast<unsigned*>(sm);                 // [128][KPAD]
    unsigned* qu   = reinterpret_cast<unsigned*>(sm + S_KEYS_SZ);     // [8][64]
    unsigned* w3u  = reinterpret_cast<unsigned*>(sm + S_KEYS_SZ + S_QH_SZ); // [64]

    int b  = blockIdx.z;
    int q0 = blockIdx.y * 8;
    int k0 = blockIdx.x * 128;
    int tid = threadIdx.x;

    // stage q rows (8 x 64 half2)
    {
        int r = tid >> 6, l2 = tid & 63;
        qu[tid] = reinterpret_cast<const unsigned*>(
            q_h_g + (b * TOUT + q0 + r) * LH)[l2];
    }
    if (tid < 64) {
        float2 v = *reinterpret_cast<const float2*>(&W3[2 * tid]);
        __half2 h = __floats2half2_rn(v.x, v.y);
        w3u[tid] = *reinterpret_cast<unsigned*>(&h);
    }
    // stage 128 key rows as half2 with pad (uint2 = 2 half2 per load/store)
    for (int i = tid; i < 128 * 32; i += 512) {
        int k = i >> 5, l4 = i & 31;
        uint2 v = reinterpret_cast<const uint2*>(
            keys_h_g + (b * TIN + k0 + k) * LH)[l4];
        *reinterpret_cast<uint2*>(&keyu[k * KPAD + l4 * 2]) = v;
    }
    __syncthreads();

    int ql = tid >> 6;            // 0..7
    int kk = tid & 63;            // keys kk and kk+64
    const unsigned* qrow = qu + ql * 64;

    float accf0 = 0.0f, accf1 = 0.0f;
    #pragma unroll
    for (int g = 0; g < 8; g++) {
        __half2 a0 = __floats2half2_rn(0.f, 0.f);
        __half2 a1 = a0;
        #pragma unroll
        for (int u = 0; u < 8; u += 2) {
            int l2 = g * 8 + u;
            uint2 kv0 = *reinterpret_cast<const uint2*>(&keyu[kk * KPAD + l2]);
            uint2 kv1 = *reinterpret_cast<const uint2*>(&keyu[(kk + 64) * KPAD + l2]);
            uint2 qv  = *reinterpret_cast<const uint2*>(&qrow[l2]);
            uint2 wv  = *reinterpret_cast<const uint2*>(&w3u[l2]);
            a0 = __hfma2(tanh_h2(__hadd2(u2h2(kv0.x), u2h2(qv.x))), u2h2(wv.x), a0);
            a0 = __hfma2(tanh_h2(__hadd2(u2h2(kv0.y), u2h2(qv.y))), u2h2(wv.y), a0);
            a1 = __hfma2(tanh_h2(__hadd2(u2h2(kv1.x), u2h2(qv.x))), u2h2(wv.x), a1);
            a1 = __hfma2(tanh_h2(__hadd2(u2h2(kv1.y), u2h2(qv.y))), u2h2(wv.y), a1);
        }
        float2 f0 = __half22float2(a0); accf0 += f0.x + f0.y;
        float2 f1 = __half22float2(a1); accf1 += f1.x + f1.y;
    }
    float* orow = sc_g + (b * TOUT + q0 + ql) * TIN + k0;
    orow[kk]      = accf0;
    orow[kk + 64] = accf1;
}

// ---------------------------------------------------------------------------
// K5: softmax over 512, one warp per row. 256 CTAs x 256 thr.
// ---------------------------------------------------------------------------
__global__ void __launch_bounds__(256) softmax_kernel(
    const float* __restrict__ sc_g, float* __restrict__ attn)
{
    int row = blockIdx.x * 8 + (threadIdx.x >> 5);
    int lane = threadIdx.x & 31;
    const float* r = sc_g + row * TIN;
    float v[16], mx = -1e30f;
    #pragma unroll
    for (int i = 0; i < 16; i++) {
        v[i] = r[lane + 32 * i];
        mx = fmaxf(mx, v[i]);
    }
    #pragma unroll
    for (int off = 16; off >= 1; off >>= 1)
        mx = fmaxf(mx, __shfl_xor_sync(0xffffffffu, mx, off));
    float s = 0.0f;
    #pragma unroll
    for (int i = 0; i < 16; i++) {
        v[i] = __expf(v[i] - mx);
        s += v[i];
    }
    #pragma unroll
    for (int off = 16; off >= 1; off >>= 1)
        s += __shfl_xor_sync(0xffffffffu, s, off);
    float inv = 1.0f / s;
    float* o = attn + row * TIN;
    #pragma unroll
    for (int i = 0; i < 16; i++)
        o[lane + 32 * i] = v[i] * inv;
}

// ---------------------------------------------------------------------------
// K6: weighted = attn @ attended (R3 scalar version, proven).
// ---------------------------------------------------------------------------
__global__ void __launch_bounds__(256) weighted_kernel(
    const float* __restrict__ attn, const float* __restrict__ att,
    float* __restrict__ out)
{
    int b  = blockIdx.y;
    int q0 = blockIdx.x * 16;
    int tid = threadIdx.x;

    __shared__ float a_s[16][TIN];
    for (int i = tid; i < 16 * TIN; i += 256) {
        int r = i >> 9, kk = i & 511;
        a_s[r][kk] = attn[(b * TOUT + q0 + r) * TIN + kk];
    }
    __syncthreads();

    int d = tid & 127;
    int g = tid >> 7;
    float acc[8];
    #pragma unroll
    for (int i = 0; i < 8; i++) acc[i] = 0.0f;

    const float* ap = att + b * TIN * DATT + d;
    #pragma unroll 4
    for (int k = 0; k < TIN; k++) {
        float av = ap[k * DATT];
        #pragma unroll
        for (int i = 0; i < 8; i++)
            acc[i] += a_s[g * 8 + i][k] * av;
    }
    #pragma unroll
    for (int i = 0; i < 8; i++)
        out[(b * TOUT + q0 + g * 8 + i) * (LH + DATT) + LH + d] = acc[i];
}

// ---------------------------------------------------------------------------
extern "C" void kernel_launch(void* const* d_in, const int* in_sizes, int n_in,
                              void* d_out, int out_size)
{
    const float* inputs   = (const float*)d_in[0];
    const float* attended = (const float*)d_in[1];
    const float* Wk       = (const float*)d_in[2];
    const float* Wr       = (const float*)d_in[3];
    const float* lbias    = (const float*)d_in[4];
    const float* W1       = (const float*)d_in[5];
    const float* b1       = (const float*)d_in[6];
    const float* W2       = (const float*)d_in[7];
    const float* b2       = (const float*)d_in[8];
    const float* W3       = (const float*)d_in[9];
    float* out = (float*)d_out;

    cudaFuncSetAttribute(lstm_kernel,
                         cudaFuncAttributeMaxDynamicSharedMemorySize, LSTM_DSMEM);
    cudaFuncSetAttribute(score_kernel,
                         cudaFuncAttributeMaxDynamicSharedMemorySize, SCORE_DSMEM);

    proj_kernel<<<NB * TIN + NB * TOUT, 128>>>(attended, W1, b1, g_keys_h,
                                               inputs, Wk, lbias, g_xz);
    lstm_kernel<<<NB, 512, LSTM_DSMEM>>>(g_xz, Wr, out);
    q_kernel<<<NB * TOUT, 128>>>(out, W2, b2, g_q_h);
    {
        dim3 grid(TIN / 128, TOUT / 8, NB);
        score_kernel<<<grid, 512, SCORE_DSMEM>>>(g_keys_h, g_q_h, W3, g_sc);
    }
    softmax_kernel<<<NB * TOUT / 8, 256>>>(g_sc, g_attn);
    {
        dim3 grid(16, NB);
        weighted_kernel<<<grid, 256>>>(g_attn, attended, out);
    }
    (void)in_sizes; (void)n_in; (void)out_size;
}

// round 6
// speedup vs baseline: 1.3512x; 1.0494x over previous
#include <cuda_runtime.h>
#include <cuda_fp16.h>

#define NB   8
#define TOUT 256
#define TIN  512
#define LH   128
#define G4   512
#define DIN  128
#define DATT 128

#define OUT_X_ELEMS (NB*TOUT*(LH+DATT))
#define OUT_H_OFF   (OUT_X_ELEMS)
#define OUT_C_OFF   (OUT_X_ELEMS + NB*LH)

// ---- LSTM config ----
#define KREG 80
#define KSM  (LH - KREG)                 // 48
#define WSTRIDE 52
#define LSTM_DSMEM (512 * WSTRIDE * 4)   // 106496 B

// ---- score config ----
#define KPW  68                          // key row stride in words (half2)
#define KP4  17                          // ... in uint4
#define S_KEYS_SZ (128 * KPW * 4)        // 34816
#define S_Q_SZ    (8 * 64 * 4)           // 2048
#define S_W3_SZ   (64 * 4)               // 256
#define SCORE_DSMEM (S_KEYS_SZ + S_Q_SZ + S_W3_SZ)   // 37120

__device__ float  g_xz[NB*TOUT*G4];
__device__ __half g_keys_h[NB*TIN*LH];
__device__ __half g_q_h[NB*TOUT*LH];
__device__ float  g_sc[NB*TOUT*TIN];

__device__ __forceinline__ float tanh_hw(float x) {
    float y;
    asm("tanh.approx.f32 %0, %1;" : "=f"(y) : "f"(x));
    return y;
}
__device__ __forceinline__ float sigm_hw(float x) {
    return fmaf(0.5f, tanh_hw(0.5f * x), 0.5f);
}
__device__ __forceinline__ unsigned tanh_u2(unsigned x) {
    unsigned r;
    asm("tanh.approx.f16x2 %0, %1;" : "=r"(r) : "r"(x));
    return r;
}
__device__ __forceinline__ __half2 u2h2(unsigned u) {
    __half2 h; *reinterpret_cast<unsigned*>(&h) = u; return h;
}
__device__ __forceinline__ unsigned hadd2u(unsigned a, unsigned b) {
    __half2 r = __hadd2(u2h2(a), u2h2(b));
    return *reinterpret_cast<unsigned*>(&r);
}

// ---------------------------------------------------------------------------
// K1: fused projections, tiled.
//   bid < 256 : keys tile (16 rows x 128), 128 thr
//   else      : xz tile (8 rows x 512), 128 thr (4 cols/thread)
// ---------------------------------------------------------------------------
__global__ void __launch_bounds__(128) proj_kernel(
    const float* __restrict__ att, const float* __restrict__ W1,
    const float* __restrict__ b1,  __half* __restrict__ keys_h,
    const float* __restrict__ inp, const float* __restrict__ Wk,
    const float* __restrict__ lbias, float* __restrict__ xz)
{
    int bid = blockIdx.x;
    int j = threadIdx.x;
    if (bid < 256) {
        __shared__ float a_s[16][DATT];
        int row0 = bid * 16;
        for (int i = j; i < 16 * DATT; i += 128) {
            int r = i >> 7, d = i & 127;
            a_s[r][d] = att[(row0 + r) * DATT + d];
        }
        __syncthreads();
        float acc[16];
        float bj = b1[j];
        #pragma unroll
        for (int r = 0; r < 16; r++) acc[r] = bj;
        for (int l = 0; l < DATT; l++) {
            float wl = W1[l * LH + j];
            #pragma unroll
            for (int r = 0; r < 16; r++)
                acc[r] += a_s[r][l] * wl;
        }
        #pragma unroll
        for (int r = 0; r < 16; r++)
            keys_h[(row0 + r) * LH + j] = __float2half(acc[r]);
    } else {
        __shared__ float a_s[8][DIN];
        int row0 = (bid - 256) * 8;
        for (int i = j; i < 8 * DIN; i += 128) {
            int r = i >> 7, d = i & 127;
            a_s[r][d] = inp[(row0 + r) * DIN + d];
        }
        __syncthreads();
        float acc[4][8];
        #pragma unroll
        for (int c = 0; c < 4; c++) {
            float bc = lbias[j + c * 128];
            #pragma unroll
            for (int r = 0; r < 8; r++) acc[c][r] = bc;
        }
        for (int d = 0; d < DIN; d++) {
            float w0 = Wk[d * G4 + j];
            float w1 = Wk[d * G4 + j + 128];
            float w2 = Wk[d * G4 + j + 256];
            float w3 = Wk[d * G4 + j + 384];
            #pragma unroll
            for (int r = 0; r < 8; r++) {
                float av = a_s[r][d];
                acc[0][r] += av * w0;
                acc[1][r] += av * w1;
                acc[2][r] += av * w2;
                acc[3][r] += av * w3;
            }
        }
        #pragma unroll
        for (int r = 0; r < 8; r++) {
            float* o = xz + (row0 + r) * G4;
            o[j] = acc[0][r]; o[j + 128] = acc[1][r];
            o[j + 256] = acc[2][r]; o[j + 384] = acc[3][r];
        }
    }
}

// ---------------------------------------------------------------------------
// K2: LSTM scan (unchanged from R5 — at FFMA issue floor).
// ---------------------------------------------------------------------------
__global__ void __launch_bounds__(512, 1) lstm_kernel(
    const float* __restrict__ xz, const float* __restrict__ Wr,
    float* __restrict__ out)
{
    int b = blockIdx.x;
    int j = threadIdx.x;
    __shared__ float h_s[LH];
    __shared__ float z_s[G4];
    extern __shared__ float w_sT[];

    #pragma unroll 4
    for (int kk = 0; kk < KSM; kk++)
        w_sT[j * WSTRIDE + kk] = Wr[(KREG + kk) * G4 + j];

    float wr[KREG];
    #pragma unroll
    for (int k = 0; k < KREG; k++)
        wr[k] = Wr[k * G4 + j];

    if (j < LH) h_s[j] = 0.0f;
    float c = 0.0f;
    __syncthreads();

    const float* xzb = xz + b * TOUT * G4;
    float xnext = xzb[j];
    bool is_g = (j >= 2 * LH) && (j < 3 * LH);

    for (int t = 0; t < TOUT; t++) {
        float acc0 = xnext;
        float acc1 = 0.0f;
        if (t + 1 < TOUT) xnext = xzb[(t + 1) * G4 + j];

        #pragma unroll
        for (int kk = 0; kk < KREG / 4; kk++) {
            float4 h4 = *reinterpret_cast<const float4*>(&h_s[kk * 4]);
            acc0 += h4.x * wr[kk * 4 + 0];
            acc1 += h4.y * wr[kk * 4 + 1];
            acc0 += h4.z * wr[kk * 4 + 2];
            acc1 += h4.w * wr[kk * 4 + 3];
        }
        #pragma unroll
        for (int kk = 0; kk < KSM / 4; kk++) {
            float4 h4 = *reinterpret_cast<const float4*>(&h_s[KREG + kk * 4]);
            float4 w4 = *reinterpret_cast<const float4*>(&w_sT[j * WSTRIDE + kk * 4]);
            acc0 += h4.x * w4.x;
            acc1 += h4.y * w4.y;
            acc0 += h4.z * w4.z;
            acc1 += h4.w * w4.w;
        }
        float z = acc0 + acc1;
        z_s[j] = is_g ? tanh_hw(z) : sigm_hw(z);
        __syncthreads();
        if (j < LH) {
            c = z_s[LH + j] * c + z_s[j] * z_s[2 * LH + j];
            float h = z_s[3 * LH + j] * tanh_hw(c);
            h_s[j] = h;
            out[(b * TOUT + t) * (LH + DATT) + j] = h;
        }
        __syncthreads();
    }
    if (j < LH) {
        out[OUT_H_OFF + b * LH + j] = h_s[j];
        out[OUT_C_OFF + b * LH + j] = c;
    }
}

// ---------------------------------------------------------------------------
// K3: q = x @ W2 + b2 -> half, tiled 16 rows/CTA.
// ---------------------------------------------------------------------------
__global__ void __launch_bounds__(128) q_kernel(
    const float* __restrict__ out, const float* __restrict__ W2,
    const float* __restrict__ b2, __half* __restrict__ q_h)
{
    int row0 = blockIdx.x * 16;
    int j = threadIdx.x;
    __shared__ float x_s[16][LH];
    for (int i = j; i < 16 * LH; i += 128) {
        int r = i >> 7, l = i & 127;
        x_s[r][l] = out[(row0 + r) * (LH + DATT) + l];
    }
    __syncthreads();
    float acc[16];
    float bj = b2[j];
    #pragma unroll
    for (int r = 0; r < 16; r++) acc[r] = bj;
    for (int l = 0; l < LH; l++) {
        float wl = W2[l * LH + j];
        #pragma unroll
        for (int r = 0; r < 16; r++)
            acc[r] += x_s[r][l] * wl;
    }
    #pragma unroll
    for (int r = 0; r < 16; r++)
        q_h[(row0 + r) * LH + j] = __float2half(acc[r]);
}

// ---------------------------------------------------------------------------
// K4: raw scores. 1024 CTAs x 256 thr, 4 key-chains/thread (ILP),
//     uint4 LDS (KPW=68 words -> conflict-free per quarter-warp phase).
// ---------------------------------------------------------------------------
__global__ void __launch_bounds__(256, 4) score_kernel(
    const __half* __restrict__ keys_h_g, const __half* __restrict__ q_h_g,
    const float* __restrict__ W3, float* __restrict__ sc_g)
{
    extern __shared__ char sm[];
    uint4*    keyv = reinterpret_cast<uint4*>(sm);                  // [128][KP4]
    uint4*    qv   = reinterpret_cast<uint4*>(sm + S_KEYS_SZ);      // [8][16]
    uint4*    w3v  = reinterpret_cast<uint4*>(sm + S_KEYS_SZ + S_Q_SZ); // [16]
    unsigned* w3w  = reinterpret_cast<unsigned*>(sm + S_KEYS_SZ + S_Q_SZ);

    int b  = blockIdx.z;
    int q0 = blockIdx.y * 8;
    int k0 = blockIdx.x * 128;
    int tid = threadIdx.x;

    const uint4* kg = reinterpret_cast<const uint4*>(keys_h_g + (b * TIN + k0) * LH);
    for (int i = tid; i < 128 * 16; i += 256) {
        int k = i >> 4, c = i & 15;
        keyv[k * KP4 + c] = kg[k * 16 + c];
    }
    if (tid < 128) {
        int r = tid >> 4, c = tid & 15;
        qv[r * 16 + c] = reinterpret_cast<const uint4*>(
            q_h_g + (b * TOUT + q0 + r) * LH)[c];
    }
    if (tid < 64) {
        float2 v = *reinterpret_cast<const float2*>(&W3[2 * tid]);
        __half2 h = __floats2half2_rn(v.x, v.y);
        w3w[tid] = *reinterpret_cast<unsigned*>(&h);
    }
    __syncthreads();

    int ql = tid >> 5;            // warp-uniform q row
    int kk = tid & 31;            // chains: kk, +32, +64, +96
    const uint4* qrow = qv + ql * 16;

    float f0 = 0.f, f1 = 0.f, f2 = 0.f, f3 = 0.f;
    #pragma unroll
    for (int g2 = 0; g2 < 8; g2++) {
        __half2 z = __floats2half2_rn(0.f, 0.f);
        __half2 a0 = z, a1 = z, a2 = z, a3 = z;
        #pragma unroll
        for (int gg = 0; gg < 2; gg++) {
            int g = g2 * 2 + gg;
            uint4 q4 = qrow[g];
            uint4 w4 = w3v[g];
            uint4 kA = keyv[kk * KP4 + g];
            uint4 kB = keyv[(kk + 32) * KP4 + g];
            uint4 kC = keyv[(kk + 64) * KP4 + g];
            uint4 kD = keyv[(kk + 96) * KP4 + g];
            a0 = __hfma2(u2h2(tanh_u2(hadd2u(kA.x, q4.x))), u2h2(w4.x), a0);
            a1 = __hfma2(u2h2(tanh_u2(hadd2u(kB.x, q4.x))), u2h2(w4.x), a1);
            a2 = __hfma2(u2h2(tanh_u2(hadd2u(kC.x, q4.x))), u2h2(w4.x), a2);
            a3 = __hfma2(u2h2(tanh_u2(hadd2u(kD.x, q4.x))), u2h2(w4.x), a3);
            a0 = __hfma2(u2h2(tanh_u2(hadd2u(kA.y, q4.y))), u2h2(w4.y), a0);
            a1 = __hfma2(u2h2(tanh_u2(hadd2u(kB.y, q4.y))), u2h2(w4.y), a1);
            a2 = __hfma2(u2h2(tanh_u2(hadd2u(kC.y, q4.y))), u2h2(w4.y), a2);
            a3 = __hfma2(u2h2(tanh_u2(hadd2u(kD.y, q4.y))), u2h2(w4.y), a3);
            a0 = __hfma2(u2h2(tanh_u2(hadd2u(kA.z, q4.z))), u2h2(w4.z), a0);
            a1 = __hfma2(u2h2(tanh_u2(hadd2u(kB.z, q4.z))), u2h2(w4.z), a1);
            a2 = __hfma2(u2h2(tanh_u2(hadd2u(kC.z, q4.z))), u2h2(w4.z), a2);
            a3 = __hfma2(u2h2(tanh_u2(hadd2u(kD.z, q4.z))), u2h2(w4.z), a3);
            a0 = __hfma2(u2h2(tanh_u2(hadd2u(kA.w, q4.w))), u2h2(w4.w), a0);
            a1 = __hfma2(u2h2(tanh_u2(hadd2u(kB.w, q4.w))), u2h2(w4.w), a1);
            a2 = __hfma2(u2h2(tanh_u2(hadd2u(kC.w, q4.w))), u2h2(w4.w), a2);
            a3 = __hfma2(u2h2(tanh_u2(hadd2u(kD.w, q4.w))), u2h2(w4.w), a3);
        }
        float2 t0 = __half22float2(a0); f0 += t0.x + t0.y;
        float2 t1 = __half22float2(a1); f1 += t1.x + t1.y;
        float2 t2 = __half22float2(a2); f2 += t2.x + t2.y;
        float2 t3 = __half22float2(a3); f3 += t3.x + t3.y;
    }
    float* orow = sc_g + (b * TOUT + q0 + ql) * TIN + k0;
    orow[kk]      = f0;
    orow[kk + 32] = f1;
    orow[kk + 64] = f2;
    orow[kk + 96] = f3;
}

// ---------------------------------------------------------------------------
// K5: fused softmax + weighted. Stage raw scores (16 rows), softmax in smem,
//     then weighted = attn @ attended.
// ---------------------------------------------------------------------------
__global__ void __launch_bounds__(256) weighted_kernel(
    const float* __restrict__ sc_g, const float* __restrict__ att,
    float* __restrict__ out)
{
    int b  = blockIdx.y;
    int q0 = blockIdx.x * 16;
    int tid = threadIdx.x;

    __shared__ float a_s[16][TIN];
    for (int i = tid; i < 16 * TIN; i += 256) {
        int r = i >> 9, kk = i & 511;
        a_s[r][kk] = sc_g[(b * TOUT + q0 + r) * TIN + kk];
    }
    __syncthreads();

    // softmax in smem: 8 warps, 2 rows each
    int w = tid >> 5, lane = tid & 31;
    for (int r = w; r < 16; r += 8) {
        float* row = a_s[r];
        float v[16], mx = -1e30f;
        #pragma unroll
        for (int i = 0; i < 16; i++) {
            v[i] = row[lane + 32 * i];
            mx = fmaxf(mx, v[i]);
        }
        #pragma unroll
        for (int off = 16; off >= 1; off >>= 1)
            mx = fmaxf(mx, __shfl_xor_sync(0xffffffffu, mx, off));
        float s = 0.0f;
        #pragma unroll
        for (int i = 0; i < 16; i++) {
            v[i] = __expf(v[i] - mx);
            s += v[i];
        }
        #pragma unroll
        for (int off = 16; off >= 1; off >>= 1)
            s += __shfl_xor_sync(0xffffffffu, s, off);
        float inv = 1.0f / s;
        #pragma unroll
        for (int i = 0; i < 16; i++)
            row[lane + 32 * i] = v[i] * inv;
    }
    __syncthreads();

    int d = tid & 127;
    int g = tid >> 7;
    float acc[8];
    #pragma unroll
    for (int i = 0; i < 8; i++) acc[i] = 0.0f;

    const float* ap = att + b * TIN * DATT + d;
    #pragma unroll 4
    for (int k = 0; k < TIN; k++) {
        float av = ap[k * DATT];
        #pragma unroll
        for (int i = 0; i < 8; i++)
            acc[i] += a_s[g * 8 + i][k] * av;
    }
    #pragma unroll
    for (int i = 0; i < 8; i++)
        out[(b * TOUT + q0 + g * 8 + i) * (LH + DATT) + LH + d] = acc[i];
}

// ---------------------------------------------------------------------------
extern "C" void kernel_launch(void* const* d_in, const int* in_sizes, int n_in,
                              void* d_out, int out_size)
{
    const float* inputs   = (const float*)d_in[0];
    const float* attended = (const float*)d_in[1];
    const float* Wk       = (const float*)d_in[2];
    const float* Wr       = (const float*)d_in[3];
    const float* lbias    = (const float*)d_in[4];
    const float* W1       = (const float*)d_in[5];
    const float* b1       = (const float*)d_in[6];
    const float* W2       = (const float*)d_in[7];
    const float* b2       = (const float*)d_in[8];
    const float* W3       = (const float*)d_in[9];
    float* out = (float*)d_out;

    cudaFuncSetAttribute(lstm_kernel,
                         cudaFuncAttributeMaxDynamicSharedMemorySize, LSTM_DSMEM);
    cudaFuncSetAttribute(score_kernel,
                         cudaFuncAttributeMaxDynamicSharedMemorySize, SCORE_DSMEM);

    proj_kernel<<<512, 128>>>(attended, W1, b1, g_keys_h,
                              inputs, Wk, lbias, g_xz);
    lstm_kernel<<<NB, 512, LSTM_DSMEM>>>(g_xz, Wr, out);
    q_kernel<<<NB * TOUT / 16, 128>>>(out, W2, b2, g_q_h);
    {
        dim3 grid(TIN / 128, TOUT / 8, NB);
        score_kernel<<<grid, 256, SCORE_DSMEM>>>(g_keys_h, g_q_h, W3, g_sc);
    }
    {
        dim3 grid(16, NB);
        weighted_kernel<<<grid, 256>>>(g_sc, attended, out);
    }
    (void)in_sizes; (void)n_in; (void)out_size;
}